// round 14
// baseline (speedup 1.0000x reference)
#include <cuda_runtime.h>
#include <cuda_bf16.h>
#include <cuda_fp16.h>
#include <cstdint>

#define FULLMASK 0xffffffffu

// Problem dims (static): B=4, B_dim=64 -> B_=256; N=196; C=512; H=16; hd=32
static constexpr int NWIN  = 256;
static constexpr int NTOK  = 196;
static constexpr int NHEAD = 16;
static constexpr int HD    = 32;
static constexpr int CDIM  = 512;
static constexpr int MROWS = NWIN * NTOK;        // 50176
static constexpr int XELT  = MROWS * CDIM;       // 25,690,112

// ---------------- static device scratch (no runtime allocation) -------------
__device__ float   g_K[XELT];                    // [b_,h,n,d] fp32
__device__ float   g_V[XELT];
__device__ __half  g_xh[XELT];                   // x rounded fp16
__device__ __half  g_ath[XELT];                  // attn out rounded fp16
__device__ __half  g_kwh[2*CDIM*CDIM];           // kv_w rounded fp16
__device__ __half  g_pwh[CDIM*CDIM];             // proj_w rounded fp16

// ---------------- fp32 -> fp16 rounder ---------------------------------------
__global__ void round16_kernel(const float* __restrict__ src,
                               __half* __restrict__ dst, int n4)
{
    int i = blockIdx.x * blockDim.x + threadIdx.x;
    if (i >= n4) return;
    float4 v = ((const float4*)src)[i];
    __half2* D = (__half2*)dst;
    D[2 * i]     = __halves2half2(__float2half_rn(v.x), __float2half_rn(v.y));
    D[2 * i + 1] = __halves2half2(__float2half_rn(v.z), __float2half_rn(v.w));
}

// ---------------- mma plumbing ----------------------------------------------
#define MMAF16(cc, a0, a1, a2, a3, b0, b1)                                      \
    asm volatile("mma.sync.aligned.m16n8k16.row.col.f32.f16.f16.f32 "           \
                 "{%0,%1,%2,%3}, {%4,%5,%6,%7}, {%8,%9}, {%0,%1,%2,%3};"        \
                 : "+f"((cc)[0]), "+f"((cc)[1]), "+f"((cc)[2]), "+f"((cc)[3])   \
                 : "r"(a0), "r"(a1), "r"(a2), "r"(a3), "r"(b0), "r"(b1))

#define LDSM_X4(r0, r1, r2, r3, addr)                                           \
    asm volatile("ldmatrix.sync.aligned.m8n8.x4.shared.b16 {%0,%1,%2,%3}, [%4];"\
        : "=r"(r0), "=r"(r1), "=r"(r2), "=r"(r3) : "r"(addr))

#define CP16(saddr, gptr)                                                       \
    asm volatile("cp.async.cg.shared.global [%0], [%1], 16;"                    \
        :: "r"(saddr), "l"(gptr) : "memory")

__device__ __forceinline__ uint32_t smem_u32(const void* p) {
    uint32_t a;
    asm("{ .reg .u64 t; cvta.to.shared.u64 t, %1; cvt.u32.u64 %0, t; }"
        : "=r"(a) : "l"(p));
    return a;
}

__device__ __forceinline__ uint32_t pack_h2(__half a, __half b) {
    uint16_t ua = *(uint16_t*)&a, ub = *(uint16_t*)&b;
    return ((uint32_t)ub << 16) | ua;
}

// ---------------- fp16 1-pass GEMM (K-chunk 64, 3-buffer, 1 sync/chunk) ------
static constexpr int SROW    = 36;                    // words per row
static constexpr int TILE_B  = 128 * SROW * 4;        // 18432 bytes
static constexpr int STAGE_B = 2 * TILE_B;            // 36864 bytes
static constexpr int GEMM_SMEM = 512 + 3 * STAGE_B;   // 111104 bytes

template <bool KV>
__global__ __launch_bounds__(256, 2)
void gemm_mma(const __half* __restrict__ Ah, const __half* __restrict__ Wh,
              const float* __restrict__ bias, float* __restrict__ out)
{
    extern __shared__ char smg[];
    float* bias_s = (float*)smg;
    const uint32_t swb = smem_u32(smg + 512);

    const int tid = threadIdx.x;
    const int wid = tid >> 5, lane = tid & 31;
    const int qr = lane >> 2, qc = lane & 3;
    const int n0 = blockIdx.x * 128, m0 = blockIdx.y * 128;
    const int mbase = (wid >> 2) * 64, nbase = (wid & 3) * 32;

    if (tid < 128) bias_s[tid] = bias[n0 + tid];

    const uint4* A4 = (const uint4*)Ah;
    const uint4* W4 = (const uint4*)Wh;

    auto issue_stage = [&](int kc, int s) {       // kc in K64 units
        uint32_t sb = swb + s * STAGE_B;
        #pragma unroll
        for (int it = 0; it < 4; it++) {
            int idx = tid + it * 256;
            int row = idx >> 3, c8 = idx & 7;
            uint32_t so = (uint32_t)(row * SROW + c8 * 4) * 4;
            size_t ga = (size_t)(m0 + row) * 64 + kc * 8 + c8;
            size_t gw = (size_t)(n0 + row) * 64 + kc * 8 + c8;
            CP16(sb + so,          A4 + ga);
            CP16(sb + TILE_B + so, W4 + gw);
        }
        asm volatile("cp.async.commit_group;" ::: "memory");
    };

    float c[4][4][4];
    #pragma unroll
    for (int mt = 0; mt < 4; mt++)
        #pragma unroll
        for (int nt = 0; nt < 4; nt++)
            #pragma unroll
            for (int k = 0; k < 4; k++) c[mt][nt][k] = 0.f;

    issue_stage(0, 0);
    issue_stage(1, 1);

    const int aRow = lane & 15, aKh = lane >> 4;
    const int wSub = lane >> 3;
    const int wRow = ((wSub >> 1) * 8) + (lane & 7), wKh = wSub & 1;

    for (int kc = 0; kc < 8; kc++) {
        if (kc < 7) asm volatile("cp.async.wait_group 1;" ::: "memory");
        else        asm volatile("cp.async.wait_group 0;" ::: "memory");
        __syncthreads();
        if (kc + 2 < 8) issue_stage(kc + 2, (kc + 2) % 3);

        const uint32_t tb = swb + (kc % 3) * STAGE_B;
        #pragma unroll
        for (int ks = 0; ks < 4; ks++) {
            uint32_t bh[4][2];
            #pragma unroll
            for (int np = 0; np < 2; np++) {
                uint32_t wa = tb + TILE_B +
                    (uint32_t)(((nbase + np * 16 + wRow) * SROW + ks * 8 + wKh * 4) * 4);
                LDSM_X4(bh[np*2][0], bh[np*2][1], bh[np*2+1][0], bh[np*2+1][1], wa);
            }
            #pragma unroll
            for (int mt = 0; mt < 4; mt++) {
                uint32_t aa = tb +
                    (uint32_t)(((mbase + mt * 16 + aRow) * SROW + ks * 8 + aKh * 4) * 4);
                uint32_t a0, a1, a2, a3;
                LDSM_X4(a0, a1, a2, a3, aa);
                #pragma unroll
                for (int nt = 0; nt < 4; nt++)
                    MMAF16(c[mt][nt], a0, a1, a2, a3, bh[nt][0], bh[nt][1]);
            }
        }
    }

    #pragma unroll
    for (int mt = 0; mt < 4; mt++) {
        #pragma unroll
        for (int half = 0; half < 2; half++) {
            int m = m0 + mbase + mt * 16 + qr + 8 * half;
            int b_ = m / NTOK, n = m - b_ * NTOK;
            #pragma unroll
            for (int nt = 0; nt < 4; nt++) {
                int col = n0 + nbase + nt * 8 + qc * 2;
                float2 v;
                v.x = c[mt][nt][2 * half]     + bias_s[col - n0];
                v.y = c[mt][nt][2 * half + 1] + bias_s[col - n0 + 1];
                if (KV) {
                    float* dst = (col < CDIM) ? g_K : g_V;
                    int cm = col & (CDIM - 1);
                    int h = cm >> 5, d = cm & 31;
                    *(float2*)(dst + ((size_t)((b_ * NHEAD + h) * NTOK + n)) * HD + d) = v;
                } else {
                    *(float2*)(out + (size_t)m * CDIM + col) = v;
                }
            }
        }
    }
}

// ---------------- fp16 mma attention ----------------------------------------
// One CTA per (window, head), 224 threads (7 warps), 2 strips/warp.
// Q split fp16 hi/lo (exact), K/V rounded fp16, P split fp16 hi/lo (exact).
// smem (words): Qh 4480 | Ql 4480 | Kh 4480 | Vh 4480 | bias 1184 | CT 224
static constexpr int ATTN_SMEM_B = 19328 * 4;   // 77312

__global__ __launch_bounds__(224, 2)
void attn_mma(const float* __restrict__ q_global,
              const float* __restrict__ bias_table)
{
    extern __shared__ float sm[];
    __half* Qh = (__half*)(sm);
    __half* Ql = (__half*)(sm + 4480);
    __half* Kh = (__half*)(sm + 8960);
    __half* Vh = (__half*)(sm + 13440);
    float* sBias = sm + 17920;            // 1183 used
    int*   sCT   = (int*)(sm + 19104);    // 224

    const int h = blockIdx.x, b_ = blockIdx.y;
    const int tid = threadIdx.x, lane = tid & 31, wid = tid >> 5;
    const int qr = lane >> 2, qc = lane & 3;

    const float* qp = q_global + (size_t)(((b_ >> 6) * NHEAD + h) * NTOK) * HD;
    const float* kp = g_K + (size_t)((b_ * NHEAD + h) * NTOK) * HD;
    const float* vp = g_V + (size_t)((b_ * NHEAD + h) * NTOK) * HD;

    for (int i = tid; i < 224 * 32; i += 224) {
        int row = i >> 5, d = i & 31;
        bool ok = row < NTOK;
        float qv = ok ? qp[row * 32 + d] * 0.17677669529663687f : 0.f;
        __half hh = __float2half_rn(qv);
        Qh[row * 40 + d] = hh;
        Ql[row * 40 + d] = __float2half_rn(qv - __half2float(hh));
        float kv = ok ? kp[row * 32 + d] : 0.f;
        Kh[row * 40 + d] = __float2half_rn(kv);
        float vv = ok ? vp[row * 32 + d] : 0.f;
        Vh[(row >> 1) * 80 + d * 2 + (row & 1)] = __float2half_rn(vv);
    }
    for (int i = tid; i < 1183; i += 224) sBias[i] = bias_table[i * NHEAD + h];
    {
        int cix = tid;   // 224 threads cover exactly 224 entries
        int v = 0;
        if (cix < NTOK) {
            int t = cix / 49, r = cix - t * 49, hh = r / 7, w = r - hh * 7;
            v = -(t * 169 + hh * 13 + w);
        }
        sCT[cix] = v;
    }
    __syncthreads();

    const uint32_t* Qh32 = (const uint32_t*)Qh;
    const uint32_t* Ql32 = (const uint32_t*)Ql;
    const uint32_t* Kh32 = (const uint32_t*)Kh;
    const uint32_t* Vh32 = (const uint32_t*)Vh;

    for (int strip = wid; strip < 14; strip += 7) {
        const int r0 = strip * 16;
        const int ra = r0 + qr, rb = ra + 8;
        int rtA = 591, rtB = 591;
        if (ra < NTOK) { int t = ra / 49, r = ra - t * 49, hh = r / 7, w = r - hh * 7;
                         rtA = t * 169 + hh * 13 + w + 591; }
        if (rb < NTOK) { int t = rb / 49, r = rb - t * 49, hh = r / 7, w = r - hh * 7;
                         rtB = t * 169 + hh * 13 + w + 591; }

        uint32_t qa[2][4], qe[2][4];
        #pragma unroll
        for (int kc = 0; kc < 2; kc++) {
            int b0 = (r0 + qr) * 20 + kc * 8 + qc;
            qa[kc][0] = Qh32[b0];       qa[kc][1] = Qh32[b0 + 160];
            qa[kc][2] = Qh32[b0 + 4];   qa[kc][3] = Qh32[b0 + 164];
            qe[kc][0] = Ql32[b0];       qe[kc][1] = Ql32[b0 + 160];
            qe[kc][2] = Ql32[b0 + 4];   qe[kc][3] = Ql32[b0 + 164];
        }

        float cc[28][4];
        #pragma unroll
        for (int nt = 0; nt < 28; nt++)
            #pragma unroll
            for (int k = 0; k < 4; k++) cc[nt][k] = 0.f;

        #pragma unroll
        for (int nt = 0; nt < 28; nt++) {
            int kb = (nt * 8 + qr) * 20 + qc;
            uint32_t h0 = Kh32[kb], h1 = Kh32[kb + 4], h2 = Kh32[kb + 8], h3 = Kh32[kb + 12];
            MMAF16(cc[nt], qa[0][0], qa[0][1], qa[0][2], qa[0][3], h0, h1);
            MMAF16(cc[nt], qa[1][0], qa[1][1], qa[1][2], qa[1][3], h2, h3);
            MMAF16(cc[nt], qe[0][0], qe[0][1], qe[0][2], qe[0][3], h0, h1);
            MMAF16(cc[nt], qe[1][0], qe[1][1], qe[1][2], qe[1][3], h2, h3);
        }

        // bias + mask + row max
        float mA = -1e30f, mB = -1e30f;
        #pragma unroll
        for (int nt = 0; nt < 28; nt++) {
            int c0 = nt * 8 + qc * 2;
            if (c0 < NTOK) {
                int ct = sCT[c0];
                cc[nt][0] += sBias[rtA + ct];
                cc[nt][2] += sBias[rtB + ct];
            } else { cc[nt][0] = -1e30f; cc[nt][2] = -1e30f; }
            if (c0 + 1 < NTOK) {
                int ct = sCT[c0 + 1];
                cc[nt][1] += sBias[rtA + ct];
                cc[nt][3] += sBias[rtB + ct];
            } else { cc[nt][1] = -1e30f; cc[nt][3] = -1e30f; }
            mA = fmaxf(mA, fmaxf(cc[nt][0], cc[nt][1]));
            mB = fmaxf(mB, fmaxf(cc[nt][2], cc[nt][3]));
        }
        mA = fmaxf(mA, __shfl_xor_sync(FULLMASK, mA, 1));
        mA = fmaxf(mA, __shfl_xor_sync(FULLMASK, mA, 2));
        mB = fmaxf(mB, __shfl_xor_sync(FULLMASK, mB, 1));
        mB = fmaxf(mB, __shfl_xor_sync(FULLMASK, mB, 2));

        float sumA = 0.f, sumB = 0.f;
        #pragma unroll
        for (int nt = 0; nt < 28; nt++) {
            cc[nt][0] = __expf(cc[nt][0] - mA); sumA += cc[nt][0];
            cc[nt][1] = __expf(cc[nt][1] - mA); sumA += cc[nt][1];
            cc[nt][2] = __expf(cc[nt][2] - mB); sumB += cc[nt][2];
            cc[nt][3] = __expf(cc[nt][3] - mB); sumB += cc[nt][3];
        }
        sumA += __shfl_xor_sync(FULLMASK, sumA, 1);
        sumA += __shfl_xor_sync(FULLMASK, sumA, 2);
        sumB += __shfl_xor_sync(FULLMASK, sumB, 1);
        sumB += __shfl_xor_sync(FULLMASK, sumB, 2);
        float iA = 1.f / sumA, iB = 1.f / sumB;

        float oo[4][4];
        #pragma unroll
        for (int n2 = 0; n2 < 4; n2++)
            #pragma unroll
            for (int k = 0; k < 4; k++) oo[n2][k] = 0.f;

        // interleaved: repack P (normalized, fp16 hi/lo) then PV for this t
        #pragma unroll
        for (int t = 0; t < 14; t++) {
            uint32_t ph[4], pl[4];
            #pragma unroll
            for (int half = 0; half < 2; half++) {
                float sc = half ? iB : iA;
                float x0 = cc[2 * t][2 * half] * sc, x1 = cc[2 * t][2 * half + 1] * sc;
                float y0 = cc[2 * t + 1][2 * half] * sc, y1 = cc[2 * t + 1][2 * half + 1] * sc;
                __half hx0 = __float2half_rn(x0), hx1 = __float2half_rn(x1);
                __half hy0 = __float2half_rn(y0), hy1 = __float2half_rn(y1);
                ph[half]     = pack_h2(hx0, hx1);
                ph[half + 2] = pack_h2(hy0, hy1);
                pl[half]     = pack_h2(__float2half_rn(x0 - __half2float(hx0)),
                                       __float2half_rn(x1 - __half2float(hx1)));
                pl[half + 2] = pack_h2(__float2half_rn(y0 - __half2float(hy0)),
                                       __float2half_rn(y1 - __half2float(hy1)));
            }
            #pragma unroll
            for (int n2 = 0; n2 < 4; n2++) {
                int vb = (t * 8 + qc) * 40 + n2 * 8 + qr;
                uint32_t bh0 = Vh32[vb], bh1 = Vh32[vb + 160];
                MMAF16(oo[n2], ph[0], ph[1], ph[2], ph[3], bh0, bh1);
                MMAF16(oo[n2], pl[0], pl[1], pl[2], pl[3], bh0, bh1);
            }
        }

        if (ra < NTOK) {
            size_t wb = ((size_t)(b_ * NTOK + ra)) * CDIM + h * HD;
            #pragma unroll
            for (int n2 = 0; n2 < 4; n2++) {
                int col = n2 * 8 + qc * 2;
                ((uint32_t*)g_ath)[(wb + col) >> 1] =
                    pack_h2(__float2half_rn(oo[n2][0]), __float2half_rn(oo[n2][1]));
            }
        }
        if (rb < NTOK) {
            size_t wb = ((size_t)(b_ * NTOK + rb)) * CDIM + h * HD;
            #pragma unroll
            for (int n2 = 0; n2 < 4; n2++) {
                int col = n2 * 8 + qc * 2;
                ((uint32_t*)g_ath)[(wb + col) >> 1] =
                    pack_h2(__float2half_rn(oo[n2][2]), __float2half_rn(oo[n2][3]));
            }
        }
    }
}

// ---------------------------------------------------------------------------
extern "C" void kernel_launch(void* const* d_in, const int* in_sizes, int n_in,
                              void* d_out, int out_size)
{
    const float* x      = (const float*)d_in[0];
    const float* qg     = (const float*)d_in[1];
    const float* kv_w   = (const float*)d_in[2];
    const float* kv_b   = (const float*)d_in[3];
    const float* proj_w = (const float*)d_in[4];
    const float* proj_b = (const float*)d_in[5];
    const float* btab   = (const float*)d_in[6];
    float* out = (float*)d_out;

    cudaFuncSetAttribute(attn_mma, cudaFuncAttributeMaxDynamicSharedMemorySize,
                         ATTN_SMEM_B);
    cudaFuncSetAttribute(gemm_mma<true>, cudaFuncAttributeMaxDynamicSharedMemorySize,
                         GEMM_SMEM);
    cudaFuncSetAttribute(gemm_mma<false>, cudaFuncAttributeMaxDynamicSharedMemorySize,
                         GEMM_SMEM);

    __half *xh, *kwh, *pwh, *ath;
    cudaGetSymbolAddress((void**)&xh,  g_xh);
    cudaGetSymbolAddress((void**)&kwh, g_kwh);
    cudaGetSymbolAddress((void**)&pwh, g_pwh);
    cudaGetSymbolAddress((void**)&ath, g_ath);

    int n4x = XELT / 4;
    round16_kernel<<<(n4x + 255) / 256, 256>>>(x, xh, n4x);
    int n4k = 2 * CDIM * CDIM / 4;
    round16_kernel<<<(n4k + 255) / 256, 256>>>(kv_w, kwh, n4k);
    int n4p = CDIM * CDIM / 4;
    round16_kernel<<<(n4p + 255) / 256, 256>>>(proj_w, pwh, n4p);

    dim3 gkv(2 * CDIM / 128, MROWS / 128);    // (8, 392)
    gemm_mma<true><<<gkv, 256, GEMM_SMEM>>>(xh, kwh, kv_b, nullptr);

    dim3 gat(NHEAD, NWIN);                    // (16, 256)
    attn_mma<<<gat, 224, ATTN_SMEM_B>>>(qg, btab);

    dim3 gpj(CDIM / 128, MROWS / 128);        // (4, 392)
    gemm_mma<false><<<gpj, 256, GEMM_SMEM>>>(ath, pwh, proj_b, out);
}

// round 15
// speedup vs baseline: 1.2457x; 1.2457x over previous
#include <cuda_runtime.h>
#include <cuda_bf16.h>
#include <cuda_fp16.h>
#include <cstdint>

#define FULLMASK 0xffffffffu

// Problem dims (static): B=4, B_dim=64 -> B_=256; N=196; C=512; H=16; hd=32
static constexpr int NWIN  = 256;
static constexpr int NTOK  = 196;
static constexpr int NHEAD = 16;
static constexpr int HD    = 32;
static constexpr int CDIM  = 512;
static constexpr int MROWS = NWIN * NTOK;        // 50176
static constexpr int XELT  = MROWS * CDIM;       // 25,690,112

// ---------------- static device scratch (no runtime allocation) -------------
__device__ float   g_K[XELT];                    // [b_,h,n,d] fp32
__device__ float   g_V[XELT];
__device__ __half  g_xh[XELT];                   // x rounded fp16
__device__ __half  g_ath[XELT];                  // attn out rounded fp16
__device__ __half  g_kwh[2*CDIM*CDIM];           // kv_w rounded fp16
__device__ __half  g_pwh[CDIM*CDIM];             // proj_w rounded fp16

// ---------------- fp32 -> fp16 rounder ---------------------------------------
__global__ void round16_kernel(const float* __restrict__ src,
                               __half* __restrict__ dst, int n4)
{
    int i = blockIdx.x * blockDim.x + threadIdx.x;
    if (i >= n4) return;
    float4 v = ((const float4*)src)[i];
    __half2* D = (__half2*)dst;
    D[2 * i]     = __halves2half2(__float2half_rn(v.x), __float2half_rn(v.y));
    D[2 * i + 1] = __halves2half2(__float2half_rn(v.z), __float2half_rn(v.w));
}

// ---------------- mma plumbing ----------------------------------------------
#define MMAF16(cc, a0, a1, a2, a3, b0, b1)                                      \
    asm volatile("mma.sync.aligned.m16n8k16.row.col.f32.f16.f16.f32 "           \
                 "{%0,%1,%2,%3}, {%4,%5,%6,%7}, {%8,%9}, {%0,%1,%2,%3};"        \
                 : "+f"((cc)[0]), "+f"((cc)[1]), "+f"((cc)[2]), "+f"((cc)[3])   \
                 : "r"(a0), "r"(a1), "r"(a2), "r"(a3), "r"(b0), "r"(b1))

#define LDSM_X4(r0, r1, r2, r3, addr)                                           \
    asm volatile("ldmatrix.sync.aligned.m8n8.x4.shared.b16 {%0,%1,%2,%3}, [%4];"\
        : "=r"(r0), "=r"(r1), "=r"(r2), "=r"(r3) : "r"(addr))

#define CP16(saddr, gptr)                                                       \
    asm volatile("cp.async.cg.shared.global [%0], [%1], 16;"                    \
        :: "r"(saddr), "l"(gptr) : "memory")

__device__ __forceinline__ uint32_t smem_u32(const void* p) {
    uint32_t a;
    asm("{ .reg .u64 t; cvta.to.shared.u64 t, %1; cvt.u32.u64 %0, t; }"
        : "=r"(a) : "l"(p));
    return a;
}

__device__ __forceinline__ uint32_t pack_h2(__half a, __half b) {
    uint16_t ua = *(uint16_t*)&a, ub = *(uint16_t*)&b;
    return ((uint32_t)ub << 16) | ua;
}

// ---------------- fp16 1-pass GEMM (K-chunk 64, 3-buffer, 1 sync/chunk) ------
static constexpr int SROW    = 36;                    // words per row
static constexpr int TILE_B  = 128 * SROW * 4;        // 18432 bytes
static constexpr int STAGE_B = 2 * TILE_B;            // 36864 bytes
static constexpr int GEMM_SMEM = 512 + 3 * STAGE_B;   // 111104 bytes

template <bool KV>
__global__ __launch_bounds__(256, 2)
void gemm_mma(const __half* __restrict__ Ah, const __half* __restrict__ Wh,
              const float* __restrict__ bias, float* __restrict__ out)
{
    extern __shared__ char smg[];
    float* bias_s = (float*)smg;
    const uint32_t swb = smem_u32(smg + 512);

    const int tid = threadIdx.x;
    const int wid = tid >> 5, lane = tid & 31;
    const int qr = lane >> 2, qc = lane & 3;
    const int n0 = blockIdx.x * 128, m0 = blockIdx.y * 128;
    const int mbase = (wid >> 2) * 64, nbase = (wid & 3) * 32;

    if (tid < 128) bias_s[tid] = bias[n0 + tid];

    const uint4* A4 = (const uint4*)Ah;
    const uint4* W4 = (const uint4*)Wh;

    auto issue_stage = [&](int kc, int s) {       // kc in K64 units
        uint32_t sb = swb + s * STAGE_B;
        #pragma unroll
        for (int it = 0; it < 4; it++) {
            int idx = tid + it * 256;
            int row = idx >> 3, c8 = idx & 7;
            uint32_t so = (uint32_t)(row * SROW + c8 * 4) * 4;
            size_t ga = (size_t)(m0 + row) * 64 + kc * 8 + c8;
            size_t gw = (size_t)(n0 + row) * 64 + kc * 8 + c8;
            CP16(sb + so,          A4 + ga);
            CP16(sb + TILE_B + so, W4 + gw);
        }
        asm volatile("cp.async.commit_group;" ::: "memory");
    };

    float c[4][4][4];
    #pragma unroll
    for (int mt = 0; mt < 4; mt++)
        #pragma unroll
        for (int nt = 0; nt < 4; nt++)
            #pragma unroll
            for (int k = 0; k < 4; k++) c[mt][nt][k] = 0.f;

    issue_stage(0, 0);
    issue_stage(1, 1);

    const int aRow = lane & 15, aKh = lane >> 4;
    const int wSub = lane >> 3;
    const int wRow = ((wSub >> 1) * 8) + (lane & 7), wKh = wSub & 1;

    for (int kc = 0; kc < 8; kc++) {
        if (kc < 7) asm volatile("cp.async.wait_group 1;" ::: "memory");
        else        asm volatile("cp.async.wait_group 0;" ::: "memory");
        __syncthreads();
        if (kc + 2 < 8) issue_stage(kc + 2, (kc + 2) % 3);

        const uint32_t tb = swb + (kc % 3) * STAGE_B;
        #pragma unroll
        for (int ks = 0; ks < 4; ks++) {
            uint32_t bh[4][2];
            #pragma unroll
            for (int np = 0; np < 2; np++) {
                uint32_t wa = tb + TILE_B +
                    (uint32_t)(((nbase + np * 16 + wRow) * SROW + ks * 8 + wKh * 4) * 4);
                LDSM_X4(bh[np*2][0], bh[np*2][1], bh[np*2+1][0], bh[np*2+1][1], wa);
            }
            #pragma unroll
            for (int mt = 0; mt < 4; mt++) {
                uint32_t aa = tb +
                    (uint32_t)(((mbase + mt * 16 + aRow) * SROW + ks * 8 + aKh * 4) * 4);
                uint32_t a0, a1, a2, a3;
                LDSM_X4(a0, a1, a2, a3, aa);
                #pragma unroll
                for (int nt = 0; nt < 4; nt++)
                    MMAF16(c[mt][nt], a0, a1, a2, a3, bh[nt][0], bh[nt][1]);
            }
        }
    }

    #pragma unroll
    for (int mt = 0; mt < 4; mt++) {
        #pragma unroll
        for (int half = 0; half < 2; half++) {
            int m = m0 + mbase + mt * 16 + qr + 8 * half;
            int b_ = m / NTOK, n = m - b_ * NTOK;
            #pragma unroll
            for (int nt = 0; nt < 4; nt++) {
                int col = n0 + nbase + nt * 8 + qc * 2;
                float2 v;
                v.x = c[mt][nt][2 * half]     + bias_s[col - n0];
                v.y = c[mt][nt][2 * half + 1] + bias_s[col - n0 + 1];
                if (KV) {
                    float* dst = (col < CDIM) ? g_K : g_V;
                    int cm = col & (CDIM - 1);
                    int h = cm >> 5, d = cm & 31;
                    *(float2*)(dst + ((size_t)((b_ * NHEAD + h) * NTOK + n)) * HD + d) = v;
                } else {
                    *(float2*)(out + (size_t)m * CDIM + col) = v;
                }
            }
        }
    }
}

// ---------------- fp16 mma attention (256 thr, occ 1, no reg cap) ------------
// One CTA per (window, head). Q split fp16 hi/lo (exact), K/V rounded fp16,
// P split fp16 hi/lo (exact, normalized in-repack).
// smem (words): Qh 4480 | Ql 4480 | Kh 4480 | Vh 4480 | bias 1184 | CT 224
static constexpr int ATTN_SMEM_B = 19328 * 4;   // 77312

__global__ __launch_bounds__(256, 1)
void attn_mma(const float* __restrict__ q_global,
              const float* __restrict__ bias_table)
{
    extern __shared__ float sm[];
    __half* Qh = (__half*)(sm);
    __half* Ql = (__half*)(sm + 4480);
    __half* Kh = (__half*)(sm + 8960);
    __half* Vh = (__half*)(sm + 13440);
    float* sBias = sm + 17920;            // 1183 used
    int*   sCT   = (int*)(sm + 19104);    // 224

    const int h = blockIdx.x, b_ = blockIdx.y;
    const int tid = threadIdx.x, lane = tid & 31, wid = tid >> 5;
    const int qr = lane >> 2, qc = lane & 3;

    const float* qp = q_global + (size_t)(((b_ >> 6) * NHEAD + h) * NTOK) * HD;
    const float* kp = g_K + (size_t)((b_ * NHEAD + h) * NTOK) * HD;
    const float* vp = g_V + (size_t)((b_ * NHEAD + h) * NTOK) * HD;

    for (int i = tid; i < 224 * 32; i += 256) {
        int row = i >> 5, d = i & 31;
        bool ok = row < NTOK;
        float qv = ok ? qp[row * 32 + d] * 0.17677669529663687f : 0.f;
        __half hh = __float2half_rn(qv);
        Qh[row * 40 + d] = hh;
        Ql[row * 40 + d] = __float2half_rn(qv - __half2float(hh));
        float kv = ok ? kp[row * 32 + d] : 0.f;
        Kh[row * 40 + d] = __float2half_rn(kv);
        float vv = ok ? vp[row * 32 + d] : 0.f;
        Vh[(row >> 1) * 80 + d * 2 + (row & 1)] = __float2half_rn(vv);
    }
    for (int i = tid; i < 1183; i += 256) sBias[i] = bias_table[i * NHEAD + h];
    if (tid < 224) {
        int cix = tid;
        int v = 0;
        if (cix < NTOK) {
            int t = cix / 49, r = cix - t * 49, hh = r / 7, w = r - hh * 7;
            v = -(t * 169 + hh * 13 + w);
        }
        sCT[cix] = v;
    }
    __syncthreads();

    const uint32_t* Qh32 = (const uint32_t*)Qh;
    const uint32_t* Ql32 = (const uint32_t*)Ql;
    const uint32_t* Kh32 = (const uint32_t*)Kh;
    const uint32_t* Vh32 = (const uint32_t*)Vh;

    for (int strip = wid; strip < 14; strip += 8) {
        const int r0 = strip * 16;
        const int ra = r0 + qr, rb = ra + 8;
        int rtA = 591, rtB = 591;
        if (ra < NTOK) { int t = ra / 49, r = ra - t * 49, hh = r / 7, w = r - hh * 7;
                         rtA = t * 169 + hh * 13 + w + 591; }
        if (rb < NTOK) { int t = rb / 49, r = rb - t * 49, hh = r / 7, w = r - hh * 7;
                         rtB = t * 169 + hh * 13 + w + 591; }

        uint32_t qa[2][4], qe[2][4];
        #pragma unroll
        for (int kc = 0; kc < 2; kc++) {
            int b0 = (r0 + qr) * 20 + kc * 8 + qc;
            qa[kc][0] = Qh32[b0];       qa[kc][1] = Qh32[b0 + 160];
            qa[kc][2] = Qh32[b0 + 4];   qa[kc][3] = Qh32[b0 + 164];
            qe[kc][0] = Ql32[b0];       qe[kc][1] = Ql32[b0 + 160];
            qe[kc][2] = Ql32[b0 + 4];   qe[kc][3] = Ql32[b0 + 164];
        }

        float cc[28][4];
        #pragma unroll
        for (int nt = 0; nt < 28; nt++)
            #pragma unroll
            for (int k = 0; k < 4; k++) cc[nt][k] = 0.f;

        #pragma unroll
        for (int nt = 0; nt < 28; nt++) {
            int kb = (nt * 8 + qr) * 20 + qc;
            uint32_t h0 = Kh32[kb], h1 = Kh32[kb + 4], h2 = Kh32[kb + 8], h3 = Kh32[kb + 12];
            MMAF16(cc[nt], qa[0][0], qa[0][1], qa[0][2], qa[0][3], h0, h1);
            MMAF16(cc[nt], qa[1][0], qa[1][1], qa[1][2], qa[1][3], h2, h3);
            MMAF16(cc[nt], qe[0][0], qe[0][1], qe[0][2], qe[0][3], h0, h1);
            MMAF16(cc[nt], qe[1][0], qe[1][1], qe[1][2], qe[1][3], h2, h3);
        }

        // bias + mask + row max
        float mA = -1e30f, mB = -1e30f;
        #pragma unroll
        for (int nt = 0; nt < 28; nt++) {
            int c0 = nt * 8 + qc * 2;
            if (c0 < NTOK) {
                int ct = sCT[c0];
                cc[nt][0] += sBias[rtA + ct];
                cc[nt][2] += sBias[rtB + ct];
            } else { cc[nt][0] = -1e30f; cc[nt][2] = -1e30f; }
            if (c0 + 1 < NTOK) {
                int ct = sCT[c0 + 1];
                cc[nt][1] += sBias[rtA + ct];
                cc[nt][3] += sBias[rtB + ct];
            } else { cc[nt][1] = -1e30f; cc[nt][3] = -1e30f; }
            mA = fmaxf(mA, fmaxf(cc[nt][0], cc[nt][1]));
            mB = fmaxf(mB, fmaxf(cc[nt][2], cc[nt][3]));
        }
        mA = fmaxf(mA, __shfl_xor_sync(FULLMASK, mA, 1));
        mA = fmaxf(mA, __shfl_xor_sync(FULLMASK, mA, 2));
        mB = fmaxf(mB, __shfl_xor_sync(FULLMASK, mB, 1));
        mB = fmaxf(mB, __shfl_xor_sync(FULLMASK, mB, 2));

        float sumA = 0.f, sumB = 0.f;
        #pragma unroll
        for (int nt = 0; nt < 28; nt++) {
            cc[nt][0] = __expf(cc[nt][0] - mA); sumA += cc[nt][0];
            cc[nt][1] = __expf(cc[nt][1] - mA); sumA += cc[nt][1];
            cc[nt][2] = __expf(cc[nt][2] - mB); sumB += cc[nt][2];
            cc[nt][3] = __expf(cc[nt][3] - mB); sumB += cc[nt][3];
        }
        sumA += __shfl_xor_sync(FULLMASK, sumA, 1);
        sumA += __shfl_xor_sync(FULLMASK, sumA, 2);
        sumB += __shfl_xor_sync(FULLMASK, sumB, 1);
        sumB += __shfl_xor_sync(FULLMASK, sumB, 2);
        float iA = 1.f / sumA, iB = 1.f / sumB;

        float oo[4][4];
        #pragma unroll
        for (int n2 = 0; n2 < 4; n2++)
            #pragma unroll
            for (int k = 0; k < 4; k++) oo[n2][k] = 0.f;

        // interleaved: repack P (normalized, fp16 hi/lo) then PV for this t
        #pragma unroll
        for (int t = 0; t < 14; t++) {
            uint32_t ph[4], pl[4];
            #pragma unroll
            for (int half = 0; half < 2; half++) {
                float sc = half ? iB : iA;
                float x0 = cc[2 * t][2 * half] * sc, x1 = cc[2 * t][2 * half + 1] * sc;
                float y0 = cc[2 * t + 1][2 * half] * sc, y1 = cc[2 * t + 1][2 * half + 1] * sc;
                __half hx0 = __float2half_rn(x0), hx1 = __float2half_rn(x1);
                __half hy0 = __float2half_rn(y0), hy1 = __float2half_rn(y1);
                ph[half]     = pack_h2(hx0, hx1);
                ph[half + 2] = pack_h2(hy0, hy1);
                pl[half]     = pack_h2(__float2half_rn(x0 - __half2float(hx0)),
                                       __float2half_rn(x1 - __half2float(hx1)));
                pl[half + 2] = pack_h2(__float2half_rn(y0 - __half2float(hy0)),
                                       __float2half_rn(y1 - __half2float(hy1)));
            }
            #pragma unroll
            for (int n2 = 0; n2 < 4; n2++) {
                int vb = (t * 8 + qc) * 40 + n2 * 8 + qr;
                uint32_t bh0 = Vh32[vb], bh1 = Vh32[vb + 160];
                MMAF16(oo[n2], ph[0], ph[1], ph[2], ph[3], bh0, bh1);
                MMAF16(oo[n2], pl[0], pl[1], pl[2], pl[3], bh0, bh1);
            }
        }

        if (ra < NTOK) {
            size_t wb = ((size_t)(b_ * NTOK + ra)) * CDIM + h * HD;
            #pragma unroll
            for (int n2 = 0; n2 < 4; n2++) {
                int col = n2 * 8 + qc * 2;
                ((uint32_t*)g_ath)[(wb + col) >> 1] =
                    pack_h2(__float2half_rn(oo[n2][0]), __float2half_rn(oo[n2][1]));
            }
        }
        if (rb < NTOK) {
            size_t wb = ((size_t)(b_ * NTOK + rb)) * CDIM + h * HD;
            #pragma unroll
            for (int n2 = 0; n2 < 4; n2++) {
                int col = n2 * 8 + qc * 2;
                ((uint32_t*)g_ath)[(wb + col) >> 1] =
                    pack_h2(__float2half_rn(oo[n2][2]), __float2half_rn(oo[n2][3]));
            }
        }
    }
}

// ---------------------------------------------------------------------------
extern "C" void kernel_launch(void* const* d_in, const int* in_sizes, int n_in,
                              void* d_out, int out_size)
{
    const float* x      = (const float*)d_in[0];
    const float* qg     = (const float*)d_in[1];
    const float* kv_w   = (const float*)d_in[2];
    const float* kv_b   = (const float*)d_in[3];
    const float* proj_w = (const float*)d_in[4];
    const float* proj_b = (const float*)d_in[5];
    const float* btab   = (const float*)d_in[6];
    float* out = (float*)d_out;

    cudaFuncSetAttribute(attn_mma, cudaFuncAttributeMaxDynamicSharedMemorySize,
                         ATTN_SMEM_B);
    cudaFuncSetAttribute(gemm_mma<true>, cudaFuncAttributeMaxDynamicSharedMemorySize,
                         GEMM_SMEM);
    cudaFuncSetAttribute(gemm_mma<false>, cudaFuncAttributeMaxDynamicSharedMemorySize,
                         GEMM_SMEM);

    __half *xh, *kwh, *pwh, *ath;
    cudaGetSymbolAddress((void**)&xh,  g_xh);
    cudaGetSymbolAddress((void**)&kwh, g_kwh);
    cudaGetSymbolAddress((void**)&pwh, g_pwh);
    cudaGetSymbolAddress((void**)&ath, g_ath);

    int n4x = XELT / 4;
    round16_kernel<<<(n4x + 255) / 256, 256>>>(x, xh, n4x);
    int n4k = 2 * CDIM * CDIM / 4;
    round16_kernel<<<(n4k + 255) / 256, 256>>>(kv_w, kwh, n4k);
    int n4p = CDIM * CDIM / 4;
    round16_kernel<<<(n4p + 255) / 256, 256>>>(proj_w, pwh, n4p);

    dim3 gkv(2 * CDIM / 128, MROWS / 128);    // (8, 392)
    gemm_mma<true><<<gkv, 256, GEMM_SMEM>>>(xh, kwh, kv_b, nullptr);

    dim3 gat(NHEAD, NWIN);                    // (16, 256)
    attn_mma<<<gat, 256, ATTN_SMEM_B>>>(qg, btab);

    dim3 gpj(CDIM / 128, MROWS / 128);        // (4, 392)
    gemm_mma<false><<<gpj, 256, GEMM_SMEM>>>(ath, pwh, proj_b, out);
}

// round 16
// speedup vs baseline: 1.5192x; 1.2195x over previous
#include <cuda_runtime.h>
#include <cuda_bf16.h>
#include <cuda_fp16.h>
#include <cstdint>

#define FULLMASK 0xffffffffu

// Problem dims (static): B=4, B_dim=64 -> B_=256; N=196; C=512; H=16; hd=32
static constexpr int NWIN  = 256;
static constexpr int NTOK  = 196;
static constexpr int NHEAD = 16;
static constexpr int HD    = 32;
static constexpr int CDIM  = 512;
static constexpr int MROWS = NWIN * NTOK;        // 50176
static constexpr int XELT  = MROWS * CDIM;       // 25,690,112

// ---------------- static device scratch (no runtime allocation) -------------
__device__ float   g_K[XELT];                    // [b_,h,n,d] fp32
__device__ float   g_V[XELT];
__device__ __half  g_xh[XELT];                   // x rounded fp16
__device__ __half  g_ath[XELT];                  // attn out rounded fp16
__device__ __half  g_kwh[2*CDIM*CDIM];           // kv_w rounded fp16
__device__ __half  g_pwh[CDIM*CDIM];             // proj_w rounded fp16

// ---------------- fp32 -> fp16 rounder ---------------------------------------
__global__ void round16_kernel(const float* __restrict__ src,
                               __half* __restrict__ dst, int n4)
{
    int i = blockIdx.x * blockDim.x + threadIdx.x;
    if (i >= n4) return;
    float4 v = ((const float4*)src)[i];
    __half2* D = (__half2*)dst;
    D[2 * i]     = __halves2half2(__float2half_rn(v.x), __float2half_rn(v.y));
    D[2 * i + 1] = __halves2half2(__float2half_rn(v.z), __float2half_rn(v.w));
}

// ---------------- mma plumbing ----------------------------------------------
#define MMAF16(cc, a0, a1, a2, a3, b0, b1)                                      \
    asm volatile("mma.sync.aligned.m16n8k16.row.col.f32.f16.f16.f32 "           \
                 "{%0,%1,%2,%3}, {%4,%5,%6,%7}, {%8,%9}, {%0,%1,%2,%3};"        \
                 : "+f"((cc)[0]), "+f"((cc)[1]), "+f"((cc)[2]), "+f"((cc)[3])   \
                 : "r"(a0), "r"(a1), "r"(a2), "r"(a3), "r"(b0), "r"(b1))

#define LDSM_X4(r0, r1, r2, r3, addr)                                           \
    asm volatile("ldmatrix.sync.aligned.m8n8.x4.shared.b16 {%0,%1,%2,%3}, [%4];"\
        : "=r"(r0), "=r"(r1), "=r"(r2), "=r"(r3) : "r"(addr))

#define CP16(saddr, gptr)                                                       \
    asm volatile("cp.async.cg.shared.global [%0], [%1], 16;"                    \
        :: "r"(saddr), "l"(gptr) : "memory")

__device__ __forceinline__ uint32_t smem_u32(const void* p) {
    uint32_t a;
    asm("{ .reg .u64 t; cvta.to.shared.u64 t, %1; cvt.u32.u64 %0, t; }"
        : "=r"(a) : "l"(p));
    return a;
}

__device__ __forceinline__ uint32_t pack_h2(__half a, __half b) {
    uint16_t ua = *(uint16_t*)&a, ub = *(uint16_t*)&b;
    return ((uint32_t)ub << 16) | ua;
}

// ---------------- fp16 1-pass GEMM (K-chunk 64, 3-buffer, 1 sync/chunk) ------
static constexpr int SROW    = 36;                    // words per row
static constexpr int TILE_B  = 128 * SROW * 4;        // 18432 bytes
static constexpr int STAGE_B = 2 * TILE_B;            // 36864 bytes
static constexpr int GEMM_SMEM = 512 + 3 * STAGE_B;   // 111104 bytes

template <bool KV>
__global__ __launch_bounds__(256, 2)
void gemm_mma(const __half* __restrict__ Ah, const __half* __restrict__ Wh,
              const float* __restrict__ bias, float* __restrict__ out)
{
    extern __shared__ char smg[];
    float* bias_s = (float*)smg;
    const uint32_t swb = smem_u32(smg + 512);

    const int tid = threadIdx.x;
    const int wid = tid >> 5, lane = tid & 31;
    const int qr = lane >> 2, qc = lane & 3;
    const int n0 = blockIdx.x * 128, m0 = blockIdx.y * 128;
    const int mbase = (wid >> 2) * 64, nbase = (wid & 3) * 32;

    if (tid < 128) bias_s[tid] = bias[n0 + tid];

    const uint4* A4 = (const uint4*)Ah;
    const uint4* W4 = (const uint4*)Wh;

    auto issue_stage = [&](int kc, int s) {       // kc in K64 units
        uint32_t sb = swb + s * STAGE_B;
        #pragma unroll
        for (int it = 0; it < 4; it++) {
            int idx = tid + it * 256;
            int row = idx >> 3, c8 = idx & 7;
            uint32_t so = (uint32_t)(row * SROW + c8 * 4) * 4;
            size_t ga = (size_t)(m0 + row) * 64 + kc * 8 + c8;
            size_t gw = (size_t)(n0 + row) * 64 + kc * 8 + c8;
            CP16(sb + so,          A4 + ga);
            CP16(sb + TILE_B + so, W4 + gw);
        }
        asm volatile("cp.async.commit_group;" ::: "memory");
    };

    float c[4][4][4];
    #pragma unroll
    for (int mt = 0; mt < 4; mt++)
        #pragma unroll
        for (int nt = 0; nt < 4; nt++)
            #pragma unroll
            for (int k = 0; k < 4; k++) c[mt][nt][k] = 0.f;

    issue_stage(0, 0);
    issue_stage(1, 1);

    const int aRow = lane & 15, aKh = lane >> 4;
    const int wSub = lane >> 3;
    const int wRow = ((wSub >> 1) * 8) + (lane & 7), wKh = wSub & 1;

    for (int kc = 0; kc < 8; kc++) {
        if (kc < 7) asm volatile("cp.async.wait_group 1;" ::: "memory");
        else        asm volatile("cp.async.wait_group 0;" ::: "memory");
        __syncthreads();
        if (kc + 2 < 8) issue_stage(kc + 2, (kc + 2) % 3);

        const uint32_t tb = swb + (kc % 3) * STAGE_B;
        #pragma unroll
        for (int ks = 0; ks < 4; ks++) {
            uint32_t bh[4][2];
            #pragma unroll
            for (int np = 0; np < 2; np++) {
                uint32_t wa = tb + TILE_B +
                    (uint32_t)(((nbase + np * 16 + wRow) * SROW + ks * 8 + wKh * 4) * 4);
                LDSM_X4(bh[np*2][0], bh[np*2][1], bh[np*2+1][0], bh[np*2+1][1], wa);
            }
            #pragma unroll
            for (int mt = 0; mt < 4; mt++) {
                uint32_t aa = tb +
                    (uint32_t)(((mbase + mt * 16 + aRow) * SROW + ks * 8 + aKh * 4) * 4);
                uint32_t a0, a1, a2, a3;
                LDSM_X4(a0, a1, a2, a3, aa);
                #pragma unroll
                for (int nt = 0; nt < 4; nt++)
                    MMAF16(c[mt][nt], a0, a1, a2, a3, bh[nt][0], bh[nt][1]);
            }
        }
    }

    #pragma unroll
    for (int mt = 0; mt < 4; mt++) {
        #pragma unroll
        for (int half = 0; half < 2; half++) {
            int m = m0 + mbase + mt * 16 + qr + 8 * half;
            int b_ = m / NTOK, n = m - b_ * NTOK;
            #pragma unroll
            for (int nt = 0; nt < 4; nt++) {
                int col = n0 + nbase + nt * 8 + qc * 2;
                float2 v;
                v.x = c[mt][nt][2 * half]     + bias_s[col - n0];
                v.y = c[mt][nt][2 * half + 1] + bias_s[col - n0 + 1];
                if (KV) {
                    float* dst = (col < CDIM) ? g_K : g_V;
                    int cm = col & (CDIM - 1);
                    int h = cm >> 5, d = cm & 31;
                    *(float2*)(dst + ((size_t)((b_ * NHEAD + h) * NTOK + n)) * HD + d) = v;
                } else {
                    *(float2*)(out + (size_t)m * CDIM + col) = v;
                }
            }
        }
    }
}

// ---------------- fp16 mma attention, online softmax, occ 2 ------------------
// One CTA per (window, head), 256 thr, 2 CTAs/SM.
// Columns processed in 2 chunks of 112 (14 n-tiles) with running max/sum;
// per-chunk cc[14][4] keeps regs <= 128 so occupancy 2 holds without spills.
// smem (words): Qh 4480 | Ql 4480 | Kh 4480 | Vh 4480 | bias 1184 | CT 224
static constexpr int ATTN_SMEM_B = 19328 * 4;   // 77312

__global__ __launch_bounds__(256, 2)
void attn_mma(const float* __restrict__ q_global,
              const float* __restrict__ bias_table)
{
    extern __shared__ float sm[];
    __half* Qh = (__half*)(sm);
    __half* Ql = (__half*)(sm + 4480);
    __half* Kh = (__half*)(sm + 8960);
    __half* Vh = (__half*)(sm + 13440);
    float* sBias = sm + 17920;            // 1183 used
    int*   sCT   = (int*)(sm + 19104);    // 224

    const int h = blockIdx.x, b_ = blockIdx.y;
    const int tid = threadIdx.x, lane = tid & 31, wid = tid >> 5;
    const int qr = lane >> 2, qc = lane & 3;

    const float* qp = q_global + (size_t)(((b_ >> 6) * NHEAD + h) * NTOK) * HD;
    const float* kp = g_K + (size_t)((b_ * NHEAD + h) * NTOK) * HD;
    const float* vp = g_V + (size_t)((b_ * NHEAD + h) * NTOK) * HD;

    for (int i = tid; i < 224 * 32; i += 256) {
        int row = i >> 5, d = i & 31;
        bool ok = row < NTOK;
        float qv = ok ? qp[row * 32 + d] * 0.17677669529663687f : 0.f;
        __half hh = __float2half_rn(qv);
        Qh[row * 40 + d] = hh;
        Ql[row * 40 + d] = __float2half_rn(qv - __half2float(hh));
        float kv = ok ? kp[row * 32 + d] : 0.f;
        Kh[row * 40 + d] = __float2half_rn(kv);
        float vv = ok ? vp[row * 32 + d] : 0.f;
        Vh[(row >> 1) * 80 + d * 2 + (row & 1)] = __float2half_rn(vv);
    }
    for (int i = tid; i < 1183; i += 256) sBias[i] = bias_table[i * NHEAD + h];
    if (tid < 224) {
        int cix = tid;
        int v = 0;
        if (cix < NTOK) {
            int t = cix / 49, r = cix - t * 49, hh = r / 7, w = r - hh * 7;
            v = -(t * 169 + hh * 13 + w);
        }
        sCT[cix] = v;
    }
    __syncthreads();

    const uint32_t* Qh32 = (const uint32_t*)Qh;
    const uint32_t* Ql32 = (const uint32_t*)Ql;
    const uint32_t* Kh32 = (const uint32_t*)Kh;
    const uint32_t* Vh32 = (const uint32_t*)Vh;

    for (int strip = wid; strip < 14; strip += 8) {
        const int r0 = strip * 16;
        const int ra = r0 + qr, rb = ra + 8;
        int rtA = 591, rtB = 591;
        if (ra < NTOK) { int t = ra / 49, r = ra - t * 49, hh = r / 7, w = r - hh * 7;
                         rtA = t * 169 + hh * 13 + w + 591; }
        if (rb < NTOK) { int t = rb / 49, r = rb - t * 49, hh = r / 7, w = r - hh * 7;
                         rtB = t * 169 + hh * 13 + w + 591; }

        uint32_t qa[2][4], qe[2][4];
        #pragma unroll
        for (int kc = 0; kc < 2; kc++) {
            int b0 = (r0 + qr) * 20 + kc * 8 + qc;
            qa[kc][0] = Qh32[b0];       qa[kc][1] = Qh32[b0 + 160];
            qa[kc][2] = Qh32[b0 + 4];   qa[kc][3] = Qh32[b0 + 164];
            qe[kc][0] = Ql32[b0];       qe[kc][1] = Ql32[b0 + 160];
            qe[kc][2] = Ql32[b0 + 4];   qe[kc][3] = Ql32[b0 + 164];
        }

        float mA = -1e30f, mB = -1e30f;       // running row max
        float sumA = 0.f, sumB = 0.f;         // per-lane running sum (reduce at end)
        float oo[4][4];
        #pragma unroll
        for (int n2 = 0; n2 < 4; n2++)
            #pragma unroll
            for (int k = 0; k < 4; k++) oo[n2][k] = 0.f;

        #pragma unroll
        for (int ch = 0; ch < 2; ch++) {
            float cc[14][4];
            #pragma unroll
            for (int nt = 0; nt < 14; nt++)
                #pragma unroll
                for (int k = 0; k < 4; k++) cc[nt][k] = 0.f;

            #pragma unroll
            for (int nt = 0; nt < 14; nt++) {
                int kb = ((ch * 14 + nt) * 8 + qr) * 20 + qc;
                uint32_t h0 = Kh32[kb], h1 = Kh32[kb + 4];
                uint32_t h2 = Kh32[kb + 8], h3 = Kh32[kb + 12];
                MMAF16(cc[nt], qa[0][0], qa[0][1], qa[0][2], qa[0][3], h0, h1);
                MMAF16(cc[nt], qa[1][0], qa[1][1], qa[1][2], qa[1][3], h2, h3);
                MMAF16(cc[nt], qe[0][0], qe[0][1], qe[0][2], qe[0][3], h0, h1);
                MMAF16(cc[nt], qe[1][0], qe[1][1], qe[1][2], qe[1][3], h2, h3);
            }

            // bias + mask + chunk max
            float cAm = -1e30f, cBm = -1e30f;
            #pragma unroll
            for (int nt = 0; nt < 14; nt++) {
                int c0 = (ch * 14 + nt) * 8 + qc * 2;
                if (c0 < NTOK) {
                    int ct = sCT[c0];
                    cc[nt][0] += sBias[rtA + ct];
                    cc[nt][2] += sBias[rtB + ct];
                } else { cc[nt][0] = -1e30f; cc[nt][2] = -1e30f; }
                if (c0 + 1 < NTOK) {
                    int ct = sCT[c0 + 1];
                    cc[nt][1] += sBias[rtA + ct];
                    cc[nt][3] += sBias[rtB + ct];
                } else { cc[nt][1] = -1e30f; cc[nt][3] = -1e30f; }
                cAm = fmaxf(cAm, fmaxf(cc[nt][0], cc[nt][1]));
                cBm = fmaxf(cBm, fmaxf(cc[nt][2], cc[nt][3]));
            }
            cAm = fmaxf(cAm, __shfl_xor_sync(FULLMASK, cAm, 1));
            cAm = fmaxf(cAm, __shfl_xor_sync(FULLMASK, cAm, 2));
            cBm = fmaxf(cBm, __shfl_xor_sync(FULLMASK, cBm, 1));
            cBm = fmaxf(cBm, __shfl_xor_sync(FULLMASK, cBm, 2));

            float nmA = fmaxf(mA, cAm), nmB = fmaxf(mB, cBm);
            float fA = __expf(mA - nmA), fB = __expf(mB - nmB);
            sumA *= fA; sumB *= fB;
            #pragma unroll
            for (int n2 = 0; n2 < 4; n2++) {
                oo[n2][0] *= fA; oo[n2][1] *= fA;
                oo[n2][2] *= fB; oo[n2][3] *= fB;
            }
            mA = nmA; mB = nmB;

            #pragma unroll
            for (int nt = 0; nt < 14; nt++) {
                cc[nt][0] = __expf(cc[nt][0] - mA); sumA += cc[nt][0];
                cc[nt][1] = __expf(cc[nt][1] - mA); sumA += cc[nt][1];
                cc[nt][2] = __expf(cc[nt][2] - mB); sumB += cc[nt][2];
                cc[nt][3] = __expf(cc[nt][3] - mB); sumB += cc[nt][3];
            }

            // repack (unnormalized P, fp16 hi/lo) + PV for this chunk
            #pragma unroll
            for (int t = 0; t < 7; t++) {
                uint32_t ph[4], pl[4];
                #pragma unroll
                for (int half = 0; half < 2; half++) {
                    float x0 = cc[2 * t][2 * half],     x1 = cc[2 * t][2 * half + 1];
                    float y0 = cc[2 * t + 1][2 * half], y1 = cc[2 * t + 1][2 * half + 1];
                    __half hx0 = __float2half_rn(x0), hx1 = __float2half_rn(x1);
                    __half hy0 = __float2half_rn(y0), hy1 = __float2half_rn(y1);
                    ph[half]     = pack_h2(hx0, hx1);
                    ph[half + 2] = pack_h2(hy0, hy1);
                    pl[half]     = pack_h2(__float2half_rn(x0 - __half2float(hx0)),
                                           __float2half_rn(x1 - __half2float(hx1)));
                    pl[half + 2] = pack_h2(__float2half_rn(y0 - __half2float(hy0)),
                                           __float2half_rn(y1 - __half2float(hy1)));
                }
                #pragma unroll
                for (int n2 = 0; n2 < 4; n2++) {
                    int vb = ((ch * 7 + t) * 8 + qc) * 40 + n2 * 8 + qr;
                    uint32_t bh0 = Vh32[vb], bh1 = Vh32[vb + 160];
                    MMAF16(oo[n2], ph[0], ph[1], ph[2], ph[3], bh0, bh1);
                    MMAF16(oo[n2], pl[0], pl[1], pl[2], pl[3], bh0, bh1);
                }
            }
        }

        sumA += __shfl_xor_sync(FULLMASK, sumA, 1);
        sumA += __shfl_xor_sync(FULLMASK, sumA, 2);
        sumB += __shfl_xor_sync(FULLMASK, sumB, 1);
        sumB += __shfl_xor_sync(FULLMASK, sumB, 2);
        float iA = 1.f / sumA, iB = 1.f / sumB;

        if (ra < NTOK) {
            size_t wb = ((size_t)(b_ * NTOK + ra)) * CDIM + h * HD;
            #pragma unroll
            for (int n2 = 0; n2 < 4; n2++) {
                int col = n2 * 8 + qc * 2;
                ((uint32_t*)g_ath)[(wb + col) >> 1] =
                    pack_h2(__float2half_rn(oo[n2][0] * iA),
                            __float2half_rn(oo[n2][1] * iA));
            }
        }
        if (rb < NTOK) {
            size_t wb = ((size_t)(b_ * NTOK + rb)) * CDIM + h * HD;
            #pragma unroll
            for (int n2 = 0; n2 < 4; n2++) {
                int col = n2 * 8 + qc * 2;
                ((uint32_t*)g_ath)[(wb + col) >> 1] =
                    pack_h2(__float2half_rn(oo[n2][2] * iB),
                            __float2half_rn(oo[n2][3] * iB));
            }
        }
    }
}

// ---------------------------------------------------------------------------
extern "C" void kernel_launch(void* const* d_in, const int* in_sizes, int n_in,
                              void* d_out, int out_size)
{
    const float* x      = (const float*)d_in[0];
    const float* qg     = (const float*)d_in[1];
    const float* kv_w   = (const float*)d_in[2];
    const float* kv_b   = (const float*)d_in[3];
    const float* proj_w = (const float*)d_in[4];
    const float* proj_b = (const float*)d_in[5];
    const float* btab   = (const float*)d_in[6];
    float* out = (float*)d_out;

    cudaFuncSetAttribute(attn_mma, cudaFuncAttributeMaxDynamicSharedMemorySize,
                         ATTN_SMEM_B);
    cudaFuncSetAttribute(gemm_mma<true>, cudaFuncAttributeMaxDynamicSharedMemorySize,
                         GEMM_SMEM);
    cudaFuncSetAttribute(gemm_mma<false>, cudaFuncAttributeMaxDynamicSharedMemorySize,
                         GEMM_SMEM);

    __half *xh, *kwh, *pwh, *ath;
    cudaGetSymbolAddress((void**)&xh,  g_xh);
    cudaGetSymbolAddress((void**)&kwh, g_kwh);
    cudaGetSymbolAddress((void**)&pwh, g_pwh);
    cudaGetSymbolAddress((void**)&ath, g_ath);

    int n4x = XELT / 4;
    round16_kernel<<<(n4x + 255) / 256, 256>>>(x, xh, n4x);
    int n4k = 2 * CDIM * CDIM / 4;
    round16_kernel<<<(n4k + 255) / 256, 256>>>(kv_w, kwh, n4k);
    int n4p = CDIM * CDIM / 4;
    round16_kernel<<<(n4p + 255) / 256, 256>>>(proj_w, pwh, n4p);

    dim3 gkv(2 * CDIM / 128, MROWS / 128);    // (8, 392)
    gemm_mma<true><<<gkv, 256, GEMM_SMEM>>>(xh, kwh, kv_b, nullptr);

    dim3 gat(NHEAD, NWIN);                    // (16, 256)
    attn_mma<<<gat, 256, ATTN_SMEM_B>>>(qg, btab);

    dim3 gpj(CDIM / 128, MROWS / 128);        // (4, 392)
    gemm_mma<false><<<gpj, 256, GEMM_SMEM>>>(ath, pwh, proj_b, out);
}